// round 16
// baseline (speedup 1.0000x reference)
#include <cuda_runtime.h>
#include <cuda_fp16.h>
#include <mma.h>
#include <math.h>
#include <float.h>

using namespace nvcuda;

// ---------------------------------------------------------------------------
// GAT 2-layer.  Softmax-aggregate raw x (pre-GEMM), apply W1 after as dense
// tensor-core GEMM (fp16 smem staging, 128 rows/block); h1 never materialized.
// CSR build forked onto a side stream, overlapped with asad.
// ---------------------------------------------------------------------------

#define MAXN 50048
#define MAXE 800000
#define MAXT (MAXE + MAXN)
#define SCANB 1024

__device__ __half g_xh[(size_t)MAXN * 64];    // x in fp16 (gather source)
__device__ __half g_xa[(size_t)MAXN * 512];   // normalized aggregated x, per head
__device__ __half g_w1h[64 * 512];            // W1 fp16
__device__ __half g_wext[64 * 16];            // W1 @ att (a_src 0-7, a_dst 8-15)
__device__ float g_as1[MAXN * 8];
__device__ float g_ad1[MAXN * 8];
__device__ int   g_deg[MAXN];
__device__ int   g_rowptr[MAXN];
__device__ int   g_cursor[MAXN];
__device__ int   g_csr[MAXT];
__device__ float g_h2v[MAXN];
__device__ unsigned g_gms[8];
__device__ unsigned g_g2[2];
__device__ int   g_total;
__device__ int   g_is64;

__device__ __forceinline__ unsigned f_enc(float f) {
    unsigned u = __float_as_uint(f);
    return (u & 0x80000000u) ? ~u : (u | 0x80000000u);
}
__device__ __forceinline__ float f_dec(unsigned e) {
    return __uint_as_float((e & 0x80000000u) ? (e & 0x7fffffffu) : ~e);
}

// ---------------------------------------------------------------------------
__global__ void k_pre(const float* __restrict__ W,
                      const float* __restrict__ att_s,
                      const float* __restrict__ att_d,
                      const unsigned int* __restrict__ edges, int E, int N) {
    int g = blockIdx.x * blockDim.x + threadIdx.x;
    int stride = gridDim.x * blockDim.x;
    for (int i = g; i < N; i += stride) g_deg[i] = 1;   // self-loop
    for (int i = g * 4; i < 64 * 512; i += stride * 4) {
        float4 v = *(const float4*)&W[i];
        __half2 p0 = __floats2half2_rn(v.x, v.y);
        __half2 p1 = __floats2half2_rn(v.z, v.w);
        *(uint2*)&g_w1h[i] = make_uint2(*(unsigned*)&p0, *(unsigned*)&p1);
    }
    for (int idx = g; idx < 64 * 16; idx += stride) {
        int k = idx >> 4, j = idx & 15;
        int head = j & 7;
        const float* att = (j < 8) ? att_s : att_d;
        float s = 0.f;
        const float* wr = &W[(size_t)k * 512 + head * 64];
        const float* ar = &att[head * 64];
        #pragma unroll 8
        for (int c = 0; c < 64; c++) s += wr[c] * ar[c];
        g_wext[k * 16 + j] = __float2half_rn(s);
    }
    if (g < 8) g_gms[g] = 0u;
    if (g < 2) g_g2[g] = 0u;
    if (g == 0) {
        g_total = 0;
        int n = E < 64 ? E : 64;
        int all0 = 1;
        for (int j = 0; j < n; j++)
            if (edges[2 * j + 1] != 0u) all0 = 0;
        g_is64 = all0;
    }
}

__global__ void k_deg(const int* __restrict__ edges, int E) {
    int e = blockIdx.x * blockDim.x + threadIdx.x;
    if (e >= E) return;
    int d = g_is64 ? (int)((const long long*)edges)[(size_t)E + e]
                   : edges[E + e];
    atomicAdd(&g_deg[d], 1);
}

// Single-kernel CSR build: block-local scan + atomic base allocation.
__global__ __launch_bounds__(SCANB) void k_build(int N) {
    __shared__ int wsum[32];
    __shared__ int base;
    int t = threadIdx.x, idx = blockIdx.x * SCANB + t;
    int d = (idx < N) ? g_deg[idx] : 0;
    int lane = t & 31, wp = t >> 5;
    int s = d;
    #pragma unroll
    for (int o = 1; o < 32; o <<= 1) {
        int u = __shfl_up_sync(0xffffffffu, s, o);
        if (lane >= o) s += u;
    }
    if (lane == 31) wsum[wp] = s;
    __syncthreads();
    if (wp == 0) {
        int w = wsum[lane];
        #pragma unroll
        for (int o = 1; o < 32; o <<= 1) {
            int u = __shfl_up_sync(0xffffffffu, w, o);
            if (lane >= o) w += u;
        }
        wsum[lane] = w;
    }
    __syncthreads();
    int incl = s + (wp > 0 ? wsum[wp - 1] : 0);
    if (t == SCANB - 1) base = atomicAdd(&g_total, incl);
    __syncthreads();
    if (idx < N) {
        int excl = base + incl - d;
        g_rowptr[idx] = excl;
        g_csr[excl]   = idx;          // self-loop edge first
        g_cursor[idx] = excl + 1;
    }
}

__global__ void k_scatter(const int* __restrict__ edges, int E) {
    int e = blockIdx.x * blockDim.x + threadIdx.x;
    if (e >= E) return;
    int s, d;
    if (g_is64) {
        s = (int)((const long long*)edges)[e];
        d = (int)((const long long*)edges)[(size_t)E + e];
    } else {
        s = edges[e];
        d = edges[E + e];
    }
    int p = atomicAdd(&g_cursor[d], 1);
    g_csr[p] = s;
}

// ---------------------------------------------------------------------------
// k_asad: x fp32 -> fp16 (g_xh) ; [64x64]@wext[64x16] -> a_src/a_dst ;
// fused per-head global max of a_src.
__global__ __launch_bounds__(256) void k_asad(const float* __restrict__ x, int N) {
    __shared__ __align__(16) __half xs[64 * 72];
    __shared__ __align__(16) __half ws[64 * 16];
    __shared__ __align__(16) float  fs[64 * 16];
    __shared__ unsigned gmx[8];

    int tid = threadIdx.x;
    int row0 = blockIdx.x * 64;

    for (int i = tid; i < 64 * 16; i += 256) {
        int r = i >> 4, c4 = (i & 15) * 4;
        float4 v = make_float4(0.f, 0.f, 0.f, 0.f);
        if (row0 + r < N) v = *(const float4*)&x[(size_t)(row0 + r) * 64 + c4];
        __half2 p0 = __floats2half2_rn(v.x, v.y);
        __half2 p1 = __floats2half2_rn(v.z, v.w);
        uint2 u = make_uint2(*(unsigned*)&p0, *(unsigned*)&p1);
        *(uint2*)&xs[r * 72 + c4] = u;
        if (row0 + r < N) *(uint2*)&g_xh[(size_t)(row0 + r) * 64 + c4] = u;
    }
    if (tid < 128) *(uint4*)&ws[tid * 8] = *(const uint4*)&g_wext[tid * 8];
    if (tid < 8) gmx[tid] = 0u;
    __syncthreads();

    int wp = tid >> 5;
    if (wp < 4) {
        wmma::fragment<wmma::accumulator, 16, 16, 16, float> c;
        wmma::fill_fragment(c, 0.f);
        #pragma unroll
        for (int k = 0; k < 4; k++) {
            wmma::fragment<wmma::matrix_a, 16, 16, 16, __half, wmma::row_major> a;
            wmma::fragment<wmma::matrix_b, 16, 16, 16, __half, wmma::row_major> b;
            wmma::load_matrix_sync(a, &xs[wp * 16 * 72 + k * 16], 72);
            wmma::load_matrix_sync(b, &ws[k * 16 * 16], 16);
            wmma::mma_sync(c, a, b, c);
        }
        wmma::store_matrix_sync(&fs[wp * 16 * 16], c, 16, wmma::mem_row_major);
    }
    __syncthreads();
    if (tid < 64) {
        int rowg = row0 + tid;
        if (rowg < N) {
            float4 s0 = *(const float4*)&fs[tid * 16 + 0];
            float4 s1 = *(const float4*)&fs[tid * 16 + 4];
            float4 d0 = *(const float4*)&fs[tid * 16 + 8];
            float4 d1 = *(const float4*)&fs[tid * 16 + 12];
            *(float4*)&g_as1[rowg * 8 + 0] = s0;
            *(float4*)&g_as1[rowg * 8 + 4] = s1;
            *(float4*)&g_ad1[rowg * 8 + 0] = d0;
            *(float4*)&g_ad1[rowg * 8 + 4] = d1;
            atomicMax(&gmx[0], f_enc(s0.x)); atomicMax(&gmx[1], f_enc(s0.y));
            atomicMax(&gmx[2], f_enc(s0.z)); atomicMax(&gmx[3], f_enc(s0.w));
            atomicMax(&gmx[4], f_enc(s1.x)); atomicMax(&gmx[5], f_enc(s1.y));
            atomicMax(&gmx[6], f_enc(s1.z)); atomicMax(&gmx[7], f_enc(s1.w));
        }
    }
    __syncthreads();
    if (tid < 8) atomicMax(&g_gms[tid], gmx[tid]);
}

// ---------------------------------------------------------------------------
// agg1: warp per node, TWO-PHASE (proven round-13 version).
__global__ __launch_bounds__(256) void k_agg1(int N) {
    __shared__ __align__(16) float wsm[8][32][8];   // [warp][edge][head]
    __shared__ int   ssm[8][32];

    int tid = threadIdx.x;
    int lane = tid & 31, wp = tid >> 5;
    int node = blockIdx.x * 8 + wp;
    if (node >= N) return;

    int start = g_rowptr[node], deg = g_deg[node];

    float adv[8], mh[8], denA[8];
    {
        float4 lo = *(const float4*)&g_ad1[node * 8];
        float4 hi = *(const float4*)&g_ad1[node * 8 + 4];
        adv[0]=lo.x; adv[1]=lo.y; adv[2]=lo.z; adv[3]=lo.w;
        adv[4]=hi.x; adv[5]=hi.y; adv[6]=hi.z; adv[7]=hi.w;
    }
    #pragma unroll
    for (int h = 0; h < 8; h++) {
        float t = f_dec(g_gms[h]) + adv[h];
        mh[h] = (t >= 0.f) ? t : 0.2f * t;
        denA[h] = 0.f;
    }

    float accx[8], accy[8];
    #pragma unroll
    for (int h = 0; h < 8; h++) { accx[h] = 0.f; accy[h] = 0.f; }

    const __half2* xh2 = (const __half2*)g_xh;

    for (int base = 0; base < deg; base += 32) {
        int idx = base + lane;
        bool valid = idx < deg;
        int s = valid ? g_csr[start + idx] : 0;
        ssm[wp][lane] = s;
        float4 alo = *(const float4*)&g_as1[s * 8];
        float4 ahi = *(const float4*)&g_as1[s * 8 + 4];
        float as[8] = {alo.x, alo.y, alo.z, alo.w, ahi.x, ahi.y, ahi.z, ahi.w};
        #pragma unroll
        for (int h = 0; h < 8; h++) {
            float e = as[h] + adv[h];
            e = (e >= 0.f) ? e : 0.2f * e;
            float w = valid ? __expf(e - mh[h]) : 0.f;
            wsm[wp][lane][h] = w;
            denA[h] += w;
        }
        __syncwarp();
        int m = deg - base; if (m > 32) m = 32;
        #pragma unroll 4
        for (int j = 0; j < m; j++) {
            int s2 = ssm[wp][j];
            float4 wlo = *(const float4*)&wsm[wp][j][0];
            float4 whi = *(const float4*)&wsm[wp][j][4];
            float2 xv = __half22float2(xh2[s2 * 32 + lane]);
            accx[0] += wlo.x * xv.x; accy[0] += wlo.x * xv.y;
            accx[1] += wlo.y * xv.x; accy[1] += wlo.y * xv.y;
            accx[2] += wlo.z * xv.x; accy[2] += wlo.z * xv.y;
            accx[3] += wlo.w * xv.x; accy[3] += wlo.w * xv.y;
            accx[4] += whi.x * xv.x; accy[4] += whi.x * xv.y;
            accx[5] += whi.y * xv.x; accy[5] += whi.y * xv.y;
            accx[6] += whi.z * xv.x; accy[6] += whi.z * xv.y;
            accx[7] += whi.w * xv.x; accy[7] += whi.w * xv.y;
        }
        __syncwarp();
    }

    #pragma unroll
    for (int h = 0; h < 8; h++) {
        float d = denA[h];
        #pragma unroll
        for (int o = 16; o; o >>= 1) d += __shfl_xor_sync(0xffffffffu, d, o);
        float inv = __fdividef(1.f, d);
        __half2 hv = __floats2half2_rn(accx[h] * inv, accy[h] * inv);
        *(__half2*)&g_xa[(size_t)node * 512 + h * 64 + 2 * lane] = hv;
    }
}

// ---------------------------------------------------------------------------
// gemm2: 128 rows/block (amortize W1 staging + barriers); fp16 smem staging.
// Warp wp owns 16-row stripe, computes all 4 col tiles per head (a-frags
// loaded once/head).  Epilogue: 2 threads/row x 32 chans; +b1, ELU, *W2 -> h2v.
__global__ __launch_bounds__(256) void k_gemm2(const float* __restrict__ b1,
                                               const float* __restrict__ W2, int N) {
    __shared__ __align__(16) __half as_[128 * 72];   // 18 KB
    __shared__ __align__(16) __half bs[64 * 72];     //  9 KB
    __shared__ __align__(16) __half fsh[128 * 72];   // 18 KB

    int tid = threadIdx.x;
    int row0 = blockIdx.x * 128;
    int wp = tid >> 5;
    int er = tid >> 1, esub = tid & 1;     // epilogue: row er, 32-chan half esub

    float h2acc = 0.f;

    for (int head = 0; head < 8; head++) {
        int col0 = head * 64;
        for (int i = tid; i < 128 * 8; i += 256) {
            int rr = i >> 3, c8 = (i & 7) * 8;
            *(uint4*)&as_[rr * 72 + c8] = *(const uint4*)&g_xa[(size_t)(row0 + rr) * 512 + col0 + c8];
        }
        for (int i = tid; i < 64 * 8; i += 256) {
            int rr = i >> 3, c8 = (i & 7) * 8;
            *(uint4*)&bs[rr * 72 + c8] = *(const uint4*)&g_w1h[(size_t)rr * 512 + col0 + c8];
        }
        __syncthreads();

        wmma::fragment<wmma::matrix_a, 16, 16, 16, __half, wmma::row_major> af[4];
        #pragma unroll
        for (int k = 0; k < 4; k++)
            wmma::load_matrix_sync(af[k], &as_[(wp * 16) * 72 + k * 16], 72);
        #pragma unroll
        for (int nt = 0; nt < 4; nt++) {
            wmma::fragment<wmma::accumulator, 16, 16, 16, float> c;
            wmma::fill_fragment(c, 0.f);
            #pragma unroll
            for (int k = 0; k < 4; k++) {
                wmma::fragment<wmma::matrix_b, 16, 16, 16, __half, wmma::row_major> b;
                wmma::load_matrix_sync(b, &bs[(k * 16) * 72 + nt * 16], 72);
                wmma::mma_sync(c, af[k], b, c);
            }
            wmma::fragment<wmma::accumulator, 16, 16, 16, __half> hfr;
            #pragma unroll
            for (int i = 0; i < hfr.num_elements; i++)
                hfr.x[i] = __float2half_rn(c.x[i]);
            wmma::store_matrix_sync(&fsh[(wp * 16) * 72 + nt * 16], hfr, 72, wmma::mem_row_major);
        }
        __syncthreads();

        // epilogue: row er, channels [esub*32, esub*32+32)
        int cb = esub * 32;
        float y[32];
        #pragma unroll
        for (int q = 0; q < 4; q++) {
            uint4 u = *(const uint4*)&fsh[er * 72 + cb + q * 8];
            const __half2* qq = (const __half2*)&u;
            #pragma unroll
            for (int k = 0; k < 4; k++) {
                float2 f = __half22float2(qq[k]);
                y[q * 8 + k * 2 + 0] = f.x;
                y[q * 8 + k * 2 + 1] = f.y;
            }
        }
        #pragma unroll
        for (int j = 0; j < 8; j++) {
            float4 bb = *(const float4*)&b1[col0 + cb + j * 4];
            float4 w2 = *(const float4*)&W2[col0 + cb + j * 4];
            float o0 = y[j*4+0] + bb.x;
            float o1 = y[j*4+1] + bb.y;
            float o2 = y[j*4+2] + bb.z;
            float o3 = y[j*4+3] + bb.w;
            o0 = (o0 > 0.f) ? o0 : expm1f(o0);
            o1 = (o1 > 0.f) ? o1 : expm1f(o1);
            o2 = (o2 > 0.f) ? o2 : expm1f(o2);
            o3 = (o3 > 0.f) ? o3 : expm1f(o3);
            h2acc += o0 * w2.x + o1 * w2.y + o2 * w2.z + o3 * w2.w;
        }
        __syncthreads();   // as_/bs/fsh reused next head
    }

    // pair reduce: lanes (2k,2k+1) share row er; both end with the row total
    h2acc += __shfl_xor_sync(0xffffffffu, h2acc, 1);
    int rowg = row0 + er;
    bool valid = rowg < N;
    if (valid && esub == 0) g_h2v[rowg] = h2acc;

    float mxv = valid ? h2acc : -FLT_MAX;
    float mnv = valid ? h2acc :  FLT_MAX;
    #pragma unroll
    for (int o = 16; o; o >>= 1) {
        mxv = fmaxf(mxv, __shfl_xor_sync(0xffffffffu, mxv, o));
        mnv = fminf(mnv, __shfl_xor_sync(0xffffffffu, mnv, o));
    }
    if ((tid & 31) == 0) {
        atomicMax(&g_g2[0], f_enc(mxv));
        atomicMax(&g_g2[1], f_enc(-mnv));
    }
}

// ---------------------------------------------------------------------------
__global__ __launch_bounds__(256) void k_agg2(const float* __restrict__ sa2p,
                                              const float* __restrict__ sd2p,
                                              const float* __restrict__ b2p,
                                              float* __restrict__ out, int N) {
    int g = blockIdx.x * 256 + threadIdx.x;
    int node = g >> 5, lane = g & 31;
    if (node >= N) return;
    float sa = sa2p[0], sd = sd2p[0];
    float gmax = f_dec(g_g2[0]);
    float gmin = -f_dec(g_g2[1]);
    int start = g_rowptr[node];
    int end = start + g_deg[node];
    float adv = g_h2v[node] * sd;

    float pre = (sa >= 0.f ? sa * gmax : sa * gmin) + adv;
    float lm = (pre >= 0.f) ? pre : 0.2f * pre;

    float den = 0.f, num = 0.f;
    for (int i = start + lane; i < end; i += 32) {
        float hv = g_h2v[g_csr[i]];
        float e = hv * sa + adv;
        e = (e >= 0.f) ? e : 0.2f * e;
        float w = __expf(e - lm);
        den += w;
        num += w * hv;
    }
    #pragma unroll
    for (int o = 16; o; o >>= 1) {
        den += __shfl_xor_sync(0xffffffffu, den, o);
        num += __shfl_xor_sync(0xffffffffu, num, o);
    }
    if (lane == 0) out[node] = num / den + b2p[0];
}

// ---------------------------------------------------------------------------
extern "C" void kernel_launch(void* const* d_in, const int* in_sizes, int n_in,
                              void* d_out, int out_size) {
    const float* x      = (const float*)d_in[0];
    const int*   edges  = (const int*)d_in[1];
    const float* W1     = (const float*)d_in[2];
    const float* att_s1 = (const float*)d_in[3];
    const float* att_d1 = (const float*)d_in[4];
    const float* b1     = (const float*)d_in[5];
    const float* W2     = (const float*)d_in[6];
    const float* att_s2 = (const float*)d_in[7];
    const float* att_d2 = (const float*)d_in[8];
    const float* b2     = (const float*)d_in[9];
    float* out = (float*)d_out;

    int N = in_sizes[0] / 64;
    int E = in_sizes[1] / 2;
    int nb = (N + SCANB - 1) / SCANB;

    static cudaStream_t s1 = nullptr;
    static cudaEvent_t evFork = nullptr, evJoin = nullptr;
    if (!s1) {
        cudaStreamCreateWithFlags(&s1, cudaStreamNonBlocking);
        cudaEventCreateWithFlags(&evFork, cudaEventDisableTiming);
        cudaEventCreateWithFlags(&evJoin, cudaEventDisableTiming);
    }

    k_pre<<<200, 256>>>(W1, att_s1, att_d1, (const unsigned int*)edges, E, N);
    cudaEventRecord(evFork, 0);
    cudaStreamWaitEvent(s1, evFork, 0);

    // side stream: CSR build chain
    k_deg<<<(E + 255) / 256, 256, 0, s1>>>(edges, E);
    k_build<<<nb, SCANB, 0, s1>>>(N);
    k_scatter<<<(E + 255) / 256, 256, 0, s1>>>(edges, E);
    cudaEventRecord(evJoin, s1);

    // main stream: x conversion + attention coefficients (independent)
    k_asad<<<(N + 63) / 64, 256>>>(x, N);

    cudaStreamWaitEvent(0, evJoin, 0);
    k_agg1<<<(N + 7) / 8, 256>>>(N);
    k_gemm2<<<(N + 127) / 128, 256>>>(b1, W2, N);
    k_agg2<<<(N * 32 + 255) / 256, 256>>>(att_s2, att_d2, b2, out, N);
}

// round 17
// speedup vs baseline: 1.0568x; 1.0568x over previous
#include <cuda_runtime.h>
#include <cuda_fp16.h>
#include <mma.h>
#include <math.h>
#include <float.h>

using namespace nvcuda;

// ---------------------------------------------------------------------------
// GAT 2-layer.  Softmax-aggregate raw x (pre-GEMM), apply W1 after as dense
// tensor-core GEMM; h1 never materialized.  agg1 phase-B uses fma.rn.f32x2.
// ELU via __expf (expm1f is a 15+-inst softseq).  CSR build on side stream.
// ---------------------------------------------------------------------------

#define MAXN 50048
#define MAXE 800000
#define MAXT (MAXE + MAXN)
#define SCANB 1024

__device__ __half g_xh[(size_t)MAXN * 64];    // x in fp16 (gather source)
__device__ __half g_xa[(size_t)MAXN * 512];   // normalized aggregated x, per head
__device__ __half g_w1h[64 * 512];            // W1 fp16
__device__ __half g_wext[64 * 16];            // W1 @ att (a_src 0-7, a_dst 8-15)
__device__ float g_as1[MAXN * 8];
__device__ float g_ad1[MAXN * 8];
__device__ int   g_deg[MAXN];
__device__ int   g_rowptr[MAXN];
__device__ int   g_cursor[MAXN];
__device__ int   g_csr[MAXT];
__device__ float g_h2v[MAXN];
__device__ unsigned g_gms[8];
__device__ unsigned g_g2[2];
__device__ int   g_total;
__device__ int   g_is64;

__device__ __forceinline__ unsigned f_enc(float f) {
    unsigned u = __float_as_uint(f);
    return (u & 0x80000000u) ? ~u : (u | 0x80000000u);
}
__device__ __forceinline__ float f_dec(unsigned e) {
    return __uint_as_float((e & 0x80000000u) ? (e & 0x7fffffffu) : ~e);
}
__device__ __forceinline__ float elu_fast(float o) {
    return (o > 0.f) ? o : (__expf(o) - 1.f);
}

// ---------------------------------------------------------------------------
__global__ void k_pre(const float* __restrict__ W,
                      const float* __restrict__ att_s,
                      const float* __restrict__ att_d,
                      const unsigned int* __restrict__ edges, int E, int N) {
    int g = blockIdx.x * blockDim.x + threadIdx.x;
    int stride = gridDim.x * blockDim.x;
    for (int i = g; i < N; i += stride) g_deg[i] = 1;   // self-loop
    for (int i = g * 4; i < 64 * 512; i += stride * 4) {
        float4 v = *(const float4*)&W[i];
        __half2 p0 = __floats2half2_rn(v.x, v.y);
        __half2 p1 = __floats2half2_rn(v.z, v.w);
        *(uint2*)&g_w1h[i] = make_uint2(*(unsigned*)&p0, *(unsigned*)&p1);
    }
    for (int idx = g; idx < 64 * 16; idx += stride) {
        int k = idx >> 4, j = idx & 15;
        int head = j & 7;
        const float* att = (j < 8) ? att_s : att_d;
        float s = 0.f;
        const float* wr = &W[(size_t)k * 512 + head * 64];
        const float* ar = &att[head * 64];
        #pragma unroll 8
        for (int c = 0; c < 64; c++) s += wr[c] * ar[c];
        g_wext[k * 16 + j] = __float2half_rn(s);
    }
    if (g < 8) g_gms[g] = 0u;
    if (g < 2) g_g2[g] = 0u;
    if (g == 0) {
        g_total = 0;
        int n = E < 64 ? E : 64;
        int all0 = 1;
        for (int j = 0; j < n; j++)
            if (edges[2 * j + 1] != 0u) all0 = 0;
        g_is64 = all0;
    }
}

// int64 indices are < 2^31: reading the low 32-bit word suffices.
__global__ void k_deg(const int* __restrict__ edges, int E) {
    int e = blockIdx.x * blockDim.x + threadIdx.x;
    if (e >= E) return;
    int d = g_is64 ? edges[2 * ((size_t)E + e)] : edges[E + e];
    atomicAdd(&g_deg[d], 1);
}

// Single-kernel CSR build: block-local scan + atomic base allocation.
__global__ __launch_bounds__(SCANB) void k_build(int N) {
    __shared__ int wsum[32];
    __shared__ int base;
    int t = threadIdx.x, idx = blockIdx.x * SCANB + t;
    int d = (idx < N) ? g_deg[idx] : 0;
    int lane = t & 31, wp = t >> 5;
    int s = d;
    #pragma unroll
    for (int o = 1; o < 32; o <<= 1) {
        int u = __shfl_up_sync(0xffffffffu, s, o);
        if (lane >= o) s += u;
    }
    if (lane == 31) wsum[wp] = s;
    __syncthreads();
    if (wp == 0) {
        int w = wsum[lane];
        #pragma unroll
        for (int o = 1; o < 32; o <<= 1) {
            int u = __shfl_up_sync(0xffffffffu, w, o);
            if (lane >= o) w += u;
        }
        wsum[lane] = w;
    }
    __syncthreads();
    int incl = s + (wp > 0 ? wsum[wp - 1] : 0);
    if (t == SCANB - 1) base = atomicAdd(&g_total, incl);
    __syncthreads();
    if (idx < N) {
        int excl = base + incl - d;
        g_rowptr[idx] = excl;
        g_csr[excl]   = idx;          // self-loop edge first
        g_cursor[idx] = excl + 1;
    }
}

__global__ void k_scatter(const int* __restrict__ edges, int E) {
    int e = blockIdx.x * blockDim.x + threadIdx.x;
    if (e >= E) return;
    int s, d;
    if (g_is64) {
        s = edges[2 * (size_t)e];
        d = edges[2 * ((size_t)E + e)];
    } else {
        s = edges[e];
        d = edges[E + e];
    }
    int p = atomicAdd(&g_cursor[d], 1);
    g_csr[p] = s;
}

// ---------------------------------------------------------------------------
// k_asad: x fp32 -> fp16 (g_xh) ; [64x64]@wext[64x16] -> a_src/a_dst ;
// fused per-head global max of a_src.
__global__ __launch_bounds__(256) void k_asad(const float* __restrict__ x, int N) {
    __shared__ __align__(16) __half xs[64 * 72];
    __shared__ __align__(16) __half ws[64 * 16];
    __shared__ __align__(16) float  fs[64 * 16];
    __shared__ unsigned gmx[8];

    int tid = threadIdx.x;
    int row0 = blockIdx.x * 64;

    for (int i = tid; i < 64 * 16; i += 256) {
        int r = i >> 4, c4 = (i & 15) * 4;
        float4 v = make_float4(0.f, 0.f, 0.f, 0.f);
        if (row0 + r < N) v = *(const float4*)&x[(size_t)(row0 + r) * 64 + c4];
        __half2 p0 = __floats2half2_rn(v.x, v.y);
        __half2 p1 = __floats2half2_rn(v.z, v.w);
        uint2 u = make_uint2(*(unsigned*)&p0, *(unsigned*)&p1);
        *(uint2*)&xs[r * 72 + c4] = u;
        if (row0 + r < N) *(uint2*)&g_xh[(size_t)(row0 + r) * 64 + c4] = u;
    }
    if (tid < 128) *(uint4*)&ws[tid * 8] = *(const uint4*)&g_wext[tid * 8];
    if (tid < 8) gmx[tid] = 0u;
    __syncthreads();

    int wp = tid >> 5;
    if (wp < 4) {
        wmma::fragment<wmma::accumulator, 16, 16, 16, float> c;
        wmma::fill_fragment(c, 0.f);
        #pragma unroll
        for (int k = 0; k < 4; k++) {
            wmma::fragment<wmma::matrix_a, 16, 16, 16, __half, wmma::row_major> a;
            wmma::fragment<wmma::matrix_b, 16, 16, 16, __half, wmma::row_major> b;
            wmma::load_matrix_sync(a, &xs[wp * 16 * 72 + k * 16], 72);
            wmma::load_matrix_sync(b, &ws[k * 16 * 16], 16);
            wmma::mma_sync(c, a, b, c);
        }
        wmma::store_matrix_sync(&fs[wp * 16 * 16], c, 16, wmma::mem_row_major);
    }
    __syncthreads();
    if (tid < 64) {
        int rowg = row0 + tid;
        if (rowg < N) {
            float4 s0 = *(const float4*)&fs[tid * 16 + 0];
            float4 s1 = *(const float4*)&fs[tid * 16 + 4];
            float4 d0 = *(const float4*)&fs[tid * 16 + 8];
            float4 d1 = *(const float4*)&fs[tid * 16 + 12];
            *(float4*)&g_as1[rowg * 8 + 0] = s0;
            *(float4*)&g_as1[rowg * 8 + 4] = s1;
            *(float4*)&g_ad1[rowg * 8 + 0] = d0;
            *(float4*)&g_ad1[rowg * 8 + 4] = d1;
            atomicMax(&gmx[0], f_enc(s0.x)); atomicMax(&gmx[1], f_enc(s0.y));
            atomicMax(&gmx[2], f_enc(s0.z)); atomicMax(&gmx[3], f_enc(s0.w));
            atomicMax(&gmx[4], f_enc(s1.x)); atomicMax(&gmx[5], f_enc(s1.y));
            atomicMax(&gmx[6], f_enc(s1.z)); atomicMax(&gmx[7], f_enc(s1.w));
        }
    }
    __syncthreads();
    if (tid < 8) atomicMax(&g_gms[tid], gmx[tid]);
}

// ---------------------------------------------------------------------------
// agg1: warp per node, two-phase.  Phase A stores weights as DUPLICATED pairs
// {w,w}; phase B accumulates with fma.rn.f32x2 (8 FFMA2/edge instead of 16 FFMA).
__global__ __launch_bounds__(256) void k_agg1(int N) {
    __shared__ __align__(16) float wsm2[8][32][16];  // [warp][edge][8 dup pairs]
    __shared__ int   ssm[8][32];

    int tid = threadIdx.x;
    int lane = tid & 31, wp = tid >> 5;
    int node = blockIdx.x * 8 + wp;
    if (node >= N) return;

    int start = g_rowptr[node], deg = g_deg[node];

    float adv[8], mh[8], denA[8];
    {
        float4 lo = *(const float4*)&g_ad1[node * 8];
        float4 hi = *(const float4*)&g_ad1[node * 8 + 4];
        adv[0]=lo.x; adv[1]=lo.y; adv[2]=lo.z; adv[3]=lo.w;
        adv[4]=hi.x; adv[5]=hi.y; adv[6]=hi.z; adv[7]=hi.w;
    }
    #pragma unroll
    for (int h = 0; h < 8; h++) {
        float t = f_dec(g_gms[h]) + adv[h];
        mh[h] = (t >= 0.f) ? t : 0.2f * t;   // leaky(upper bound) >= all logits
        denA[h] = 0.f;
    }

    unsigned long long accp[8];
    #pragma unroll
    for (int h = 0; h < 8; h++) accp[h] = 0ull;   // {0.f, 0.f}

    const __half2* xh2 = (const __half2*)g_xh;

    for (int base = 0; base < deg; base += 32) {
        // ---- phase A: this lane's edge -> 8 weights (stored as dup pairs)
        int idx = base + lane;
        bool valid = idx < deg;
        int s = valid ? g_csr[start + idx] : 0;
        ssm[wp][lane] = s;
        float4 alo = *(const float4*)&g_as1[s * 8];
        float4 ahi = *(const float4*)&g_as1[s * 8 + 4];
        float as[8] = {alo.x, alo.y, alo.z, alo.w, ahi.x, ahi.y, ahi.z, ahi.w};
        float w[8];
        #pragma unroll
        for (int h = 0; h < 8; h++) {
            float e = as[h] + adv[h];
            e = (e >= 0.f) ? e : 0.2f * e;
            w[h] = valid ? __expf(e - mh[h]) : 0.f;
            denA[h] += w[h];
        }
        *(float4*)&wsm2[wp][lane][0]  = make_float4(w[0], w[0], w[1], w[1]);
        *(float4*)&wsm2[wp][lane][4]  = make_float4(w[2], w[2], w[3], w[3]);
        *(float4*)&wsm2[wp][lane][8]  = make_float4(w[4], w[4], w[5], w[5]);
        *(float4*)&wsm2[wp][lane][12] = make_float4(w[6], w[6], w[7], w[7]);
        __syncwarp();
        // ---- phase B: this lane's 2 channels over batch edges (FFMA2)
        int m = deg - base; if (m > 32) m = 32;
        #pragma unroll 4
        for (int j = 0; j < m; j++) {
            int s2 = ssm[wp][j];
            float2 xv = __half22float2(xh2[s2 * 32 + lane]);
            unsigned long long xp;
            asm("mov.b64 %0, {%1, %2};" : "=l"(xp) : "f"(xv.x), "f"(xv.y));
            const ulonglong2* wq = (const ulonglong2*)&wsm2[wp][j][0];
            #pragma unroll
            for (int q = 0; q < 4; q++) {
                ulonglong2 u = wq[q];
                asm("fma.rn.f32x2 %0, %1, %2, %0;" : "+l"(accp[2*q])     : "l"(u.x), "l"(xp));
                asm("fma.rn.f32x2 %0, %1, %2, %0;" : "+l"(accp[2*q + 1]) : "l"(u.y), "l"(xp));
            }
        }
        __syncwarp();
    }

    // den butterfly + normalize + store (channels 2*lane, 2*lane+1 per head)
    #pragma unroll
    for (int h = 0; h < 8; h++) {
        float d = denA[h];
        #pragma unroll
        for (int o = 16; o; o >>= 1) d += __shfl_xor_sync(0xffffffffu, d, o);
        float inv = __fdividef(1.f, d);
        float ax, ay;
        asm("mov.b64 {%0, %1}, %2;" : "=f"(ax), "=f"(ay) : "l"(accp[h]));
        __half2 hv = __floats2half2_rn(ax * inv, ay * inv);
        *(__half2*)&g_xa[(size_t)node * 512 + h * 64 + 2 * lane] = hv;
    }
}

// ---------------------------------------------------------------------------
// gemm2: 128 rows/block, fp16 smem staging; epilogue +b1, ELU(__expf), *W2
// -> h2v (xa pre-normalized).  Fused h2v min/max.
__global__ __launch_bounds__(256) void k_gemm2(const float* __restrict__ b1,
                                               const float* __restrict__ W2, int N) {
    __shared__ __align__(16) __half as_[128 * 72];
    __shared__ __align__(16) __half bs[64 * 72];
    __shared__ __align__(16) __half fsh[128 * 72];

    int tid = threadIdx.x;
    int row0 = blockIdx.x * 128;
    int wp = tid >> 5;
    int er = tid >> 1, esub = tid & 1;

    float h2acc = 0.f;

    for (int head = 0; head < 8; head++) {
        int col0 = head * 64;
        for (int i = tid; i < 128 * 8; i += 256) {
            int rr = i >> 3, c8 = (i & 7) * 8;
            *(uint4*)&as_[rr * 72 + c8] = *(const uint4*)&g_xa[(size_t)(row0 + rr) * 512 + col0 + c8];
        }
        for (int i = tid; i < 64 * 8; i += 256) {
            int rr = i >> 3, c8 = (i & 7) * 8;
            *(uint4*)&bs[rr * 72 + c8] = *(const uint4*)&g_w1h[(size_t)rr * 512 + col0 + c8];
        }
        __syncthreads();

        wmma::fragment<wmma::matrix_a, 16, 16, 16, __half, wmma::row_major> af[4];
        #pragma unroll
        for (int k = 0; k < 4; k++)
            wmma::load_matrix_sync(af[k], &as_[(wp * 16) * 72 + k * 16], 72);
        #pragma unroll
        for (int nt = 0; nt < 4; nt++) {
            wmma::fragment<wmma::accumulator, 16, 16, 16, float> c;
            wmma::fill_fragment(c, 0.f);
            #pragma unroll
            for (int k = 0; k < 4; k++) {
                wmma::fragment<wmma::matrix_b, 16, 16, 16, __half, wmma::row_major> b;
                wmma::load_matrix_sync(b, &bs[(k * 16) * 72 + nt * 16], 72);
                wmma::mma_sync(c, af[k], b, c);
            }
            wmma::fragment<wmma::accumulator, 16, 16, 16, __half> hfr;
            #pragma unroll
            for (int i = 0; i < hfr.num_elements; i++)
                hfr.x[i] = __float2half_rn(c.x[i]);
            wmma::store_matrix_sync(&fsh[(wp * 16) * 72 + nt * 16], hfr, 72, wmma::mem_row_major);
        }
        __syncthreads();

        int cb = esub * 32;
        float y[32];
        #pragma unroll
        for (int q = 0; q < 4; q++) {
            uint4 u = *(const uint4*)&fsh[er * 72 + cb + q * 8];
            const __half2* qq = (const __half2*)&u;
            #pragma unroll
            for (int k = 0; k < 4; k++) {
                float2 f = __half22float2(qq[k]);
                y[q * 8 + k * 2 + 0] = f.x;
                y[q * 8 + k * 2 + 1] = f.y;
            }
        }
        #pragma unroll
        for (int j = 0; j < 8; j++) {
            float4 bb = *(const float4*)&b1[col0 + cb + j * 4];
            float4 w2 = *(const float4*)&W2[col0 + cb + j * 4];
            float o0 = elu_fast(y[j*4+0] + bb.x);
            float o1 = elu_fast(y[j*4+1] + bb.y);
            float o2 = elu_fast(y[j*4+2] + bb.z);
            float o3 = elu_fast(y[j*4+3] + bb.w);
            h2acc += o0 * w2.x + o1 * w2.y + o2 * w2.z + o3 * w2.w;
        }
        __syncthreads();   // as_/bs/fsh reused next head
    }

    h2acc += __shfl_xor_sync(0xffffffffu, h2acc, 1);
    int rowg = row0 + er;
    bool valid = rowg < N;
    if (valid && esub == 0) g_h2v[rowg] = h2acc;

    float mxv = valid ? h2acc : -FLT_MAX;
    float mnv = valid ? h2acc :  FLT_MAX;
    #pragma unroll
    for (int o = 16; o; o >>= 1) {
        mxv = fmaxf(mxv, __shfl_xor_sync(0xffffffffu, mxv, o));
        mnv = fminf(mnv, __shfl_xor_sync(0xffffffffu, mnv, o));
    }
    if ((tid & 31) == 0) {
        atomicMax(&g_g2[0], f_enc(mxv));
        atomicMax(&g_g2[1], f_enc(-mnv));
    }
}

// ---------------------------------------------------------------------------
__global__ __launch_bounds__(256) void k_agg2(const float* __restrict__ sa2p,
                                              const float* __restrict__ sd2p,
                                              const float* __restrict__ b2p,
                                              float* __restrict__ out, int N) {
    int g = blockIdx.x * 256 + threadIdx.x;
    int node = g >> 5, lane = g & 31;
    if (node >= N) return;
    float sa = sa2p[0], sd = sd2p[0];
    float gmax = f_dec(g_g2[0]);
    float gmin = -f_dec(g_g2[1]);
    int start = g_rowptr[node];
    int end = start + g_deg[node];
    float adv = g_h2v[node] * sd;

    float pre = (sa >= 0.f ? sa * gmax : sa * gmin) + adv;
    float lm = (pre >= 0.f) ? pre : 0.2f * pre;

    float den = 0.f, num = 0.f;
    for (int i = start + lane; i < end; i += 32) {
        float hv = g_h2v[g_csr[i]];
        float e = hv * sa + adv;
        e = (e >= 0.f) ? e : 0.2f * e;
        float w = __expf(e - lm);
        den += w;
        num += w * hv;
    }
    #pragma unroll
    for (int o = 16; o; o >>= 1) {
        den += __shfl_xor_sync(0xffffffffu, den, o);
        num += __shfl_xor_sync(0xffffffffu, num, o);
    }
    if (lane == 0) out[node] = num / den + b2p[0];
}

// ---------------------------------------------------------------------------
extern "C" void kernel_launch(void* const* d_in, const int* in_sizes, int n_in,
                              void* d_out, int out_size) {
    const float* x      = (const float*)d_in[0];
    const int*   edges  = (const int*)d_in[1];
    const float* W1     = (const float*)d_in[2];
    const float* att_s1 = (const float*)d_in[3];
    const float* att_d1 = (const float*)d_in[4];
    const float* b1     = (const float*)d_in[5];
    const float* W2     = (const float*)d_in[6];
    const float* att_s2 = (const float*)d_in[7];
    const float* att_d2 = (const float*)d_in[8];
    const float* b2     = (const float*)d_in[9];
    float* out = (float*)d_out;

    int N = in_sizes[0] / 64;
    int E = in_sizes[1] / 2;
    int nb = (N + SCANB - 1) / SCANB;

    static cudaStream_t s1 = nullptr;
    static cudaEvent_t evFork = nullptr, evJoin = nullptr;
    if (!s1) {
        cudaStreamCreateWithFlags(&s1, cudaStreamNonBlocking);
        cudaEventCreateWithFlags(&evFork, cudaEventDisableTiming);
        cudaEventCreateWithFlags(&evJoin, cudaEventDisableTiming);
    }

    k_pre<<<200, 256>>>(W1, att_s1, att_d1, (const unsigned int*)edges, E, N);
    cudaEventRecord(evFork, 0);
    cudaStreamWaitEvent(s1, evFork, 0);

    // side stream: CSR build chain
    k_deg<<<(E + 255) / 256, 256, 0, s1>>>(edges, E);
    k_build<<<nb, SCANB, 0, s1>>>(N);
    k_scatter<<<(E + 255) / 256, 256, 0, s1>>>(edges, E);
    cudaEventRecord(evJoin, s1);

    // main stream: x conversion + attention coefficients (independent)
    k_asad<<<(N + 63) / 64, 256>>>(x, N);

    cudaStreamWaitEvent(0, evJoin, 0);
    k_agg1<<<(N + 7) / 8, 256>>>(N);
    k_gemm2<<<(N + 127) / 128, 256>>>(b1, W2, N);
    k_agg2<<<(N * 32 + 255) / 256, 256>>>(att_s2, att_d2, b2, out, N);
}